// round 1
// baseline (speedup 1.0000x reference)
#include <cuda_runtime.h>
#include <cuda_bf16.h>
#include <math.h>

// S4D kernel init:  out[h,l] = 2 * Re( sum_n Ccf[h,n] * exp(dtA[h,n] * l) )
// Factor l = j*T + i  =>  exp(dtA*l) = P[n,j] * Q'[n,i]
//   Q[n,i] = Ccf[n] * exp(dtA*i)   (i in [0,T), T=128)
//   P[n,j] = exp(dtA * T * j)      (j in [0,L/T))
// out[h, j*T+i] = Pr*Qr - Pi*Qi  summed over n  -> small real GEMM per h.

#define N2 32
#define TT 128
#define NTHREADS 256
#define NJMAX 32

__global__ __launch_bounds__(NTHREADS)
void s4d_vandermonde_kernel(
    const float* __restrict__ log_dt,
    const float* __restrict__ C,          // (H, N2, 2)
    const float* __restrict__ log_A_real, // (H, N2)
    const float* __restrict__ A_imag,     // (H, N2)
    float* __restrict__ out,              // (H, L)
    int L, int NJ)
{
    __shared__ float2 sQ[N2][TT];     // 32 KB : Ccf * exp(dtA*i)
    __shared__ float2 sP[N2][NJMAX];  //  8 KB : exp(dtA*T*j)
    __shared__ float2 sW[N2];         // exp(dtA)
    __shared__ float  sAr[N2], sAi[N2];
    __shared__ float2 sCcf[N2];

    const int h   = blockIdx.x;
    const int tid = threadIdx.x;

    // ---------- Phase 0: per-(h,n) coefficients ----------
    if (tid < N2) {
        const int n = tid;
        const int g = h * N2 + n;
        float dt  = expf(log_dt[h]);
        float ar0 = -expf(log_A_real[g]);   // Re(A)
        float ai0 = A_imag[g];              // Im(A)
        float ar  = ar0 * dt;               // Re(dtA)
        float ai  = ai0 * dt;               // Im(dtA)
        float er  = expf(ar), s, c;
        sincosf(ai, &s, &c);
        float wr = er * c, wi = er * s;     // w = exp(dtA)
        sW[n]  = make_float2(wr, wi);
        sAr[n] = ar;
        sAi[n] = ai;
        // E = exp(dtA) - 1 ;  D = E / A  (complex divide via conj)
        float Er = wr - 1.0f, Ei = wi;
        float inv = 1.0f / (ar0 * ar0 + ai0 * ai0);
        float Dr = (Er * ar0 + Ei * ai0) * inv;
        float Di = (Ei * ar0 - Er * ai0) * inv;
        // Ccf = 2 * Cc * D   (fold the final factor 2)
        float cr = C[2 * g], ci = C[2 * g + 1];
        sCcf[n] = make_float2(2.0f * (cr * Dr - ci * Di),
                              2.0f * (cr * Di + ci * Dr));
    }
    __syncthreads();

    // ---------- Phase 1: Q[n][i] via 8 anchors + depth-16 recurrence ----------
    {
        const int n   = tid >> 3;   // 0..31
        const int seg = tid & 7;    // 0..7 -> i = 16*seg .. 16*seg+15
        float ar = sAr[n], ai = sAi[n];
        float x  = 16.0f * (float)seg;
        float e  = expf(ar * x), s, c;
        sincosf(ai * x, &s, &c);
        float zr0 = e * c, zi0 = e * s;     // exp(dtA * 16*seg)
        float2 cc = sCcf[n];
        float zr = cc.x * zr0 - cc.y * zi0; // Ccf * anchor
        float zi = cc.x * zi0 + cc.y * zr0;
        float2 w = sW[n];
        const int ibase = seg * 16;
        #pragma unroll
        for (int k = 0; k < 16; k++) {
            sQ[n][ibase + k] = make_float2(zr, zi);
            float nzr = zr * w.x - zi * w.y;
            float nzi = zr * w.y + zi * w.x;
            zr = nzr; zi = nzi;
        }
    }

    // ---------- Phase 2: P[n][j] = exp(dtA * T * j), direct (1024 elems) ----------
    for (int idx = tid; idx < N2 * NJ; idx += NTHREADS) {
        int n = idx / NJ;
        int j = idx - n * NJ;
        float x = (float)(TT * j);
        float e = expf(sAr[n] * x), s, c;
        sincosf(sAi[n] * x, &s, &c);
        sP[n][j] = make_float2(e * c, e * s);
    }
    __syncthreads();

    // ---------- Phase 3: real GEMM  out[j,i] = sum_n Pr*Qr - Pi*Qi ----------
    // Thread tile: 8 j-values x 2 i-values. 256 threads cover 32j x 128i.
    const int jt = tid >> 6;   // 0..3  -> j in [jt*8, jt*8+8)
    const int it = tid & 63;   // 0..63 -> i in {2*it, 2*it+1}

    float accr0[8], accr1[8];
    #pragma unroll
    for (int a = 0; a < 8; a++) { accr0[a] = 0.0f; accr1[a] = 0.0f; }

    #pragma unroll
    for (int n = 0; n < N2; n++) {
        // (qr0, qi0, qr1, qi1) for i = 2*it, 2*it+1
        float4 q = *(const float4*)&sQ[n][it * 2];
        #pragma unroll
        for (int jj = 0; jj < 8; jj++) {
            float2 p = sP[n][jt * 8 + jj];
            accr0[jj] = fmaf(p.x, q.x, accr0[jj]);
            accr0[jj] = fmaf(-p.y, q.y, accr0[jj]);
            accr1[jj] = fmaf(p.x, q.z, accr1[jj]);
            accr1[jj] = fmaf(-p.y, q.w, accr1[jj]);
        }
    }

    float* outh = out + (size_t)h * (size_t)L;
    #pragma unroll
    for (int jj = 0; jj < 8; jj++) {
        int j = jt * 8 + jj;
        if (j < NJ) {
            *(float2*)&outh[j * TT + it * 2] = make_float2(accr0[jj], accr1[jj]);
        }
    }
}

extern "C" void kernel_launch(void* const* d_in, const int* in_sizes, int n_in,
                              void* d_out, int out_size) {
    // inputs: [0]=L (scalar), [1]=log_dt (H), [2]=C (H,N2,2),
    //         [3]=log_A_real (H,N2), [4]=A_imag (H,N2)
    const float* log_dt     = (const float*)d_in[1];
    const float* C          = (const float*)d_in[2];
    const float* log_A_real = (const float*)d_in[3];
    const float* A_imag     = (const float*)d_in[4];
    float* out = (float*)d_out;

    int H  = in_sizes[1];          // 1024
    int L  = out_size / H;         // 4096
    int NJ = L / TT;               // 32

    s4d_vandermonde_kernel<<<H, NTHREADS>>>(log_dt, C, log_A_real, A_imag, out, L, NJ);
}

// round 2
// speedup vs baseline: 1.0694x; 1.0694x over previous
#include <cuda_runtime.h>
#include <cuda_bf16.h>
#include <math.h>

// S4D kernel init:  out[h,l] = 2 * Re( sum_n Ccf[h,n] * exp(dtA[h,n] * l) )
// Factor l = j*T + i  =>  exp(dtA*l) = P[n,j] * Q'[n,i]
//   Q[n,i] = 2*Cc*(exp(dtA)-1)/A * exp(dtA*i)   (i in [0,T), T=128)
//   P[n,j] = exp(dtA * T * j)                   (j in [0,32))
// out[h, j*T+i] = Px*Qr - Py*Qi  summed over n  -> rank-32 real contraction per h.
//
// Round-2 structure: 128 threads/block. Warp w owns j in [8w, 8w+8) so all P
// loads are warp-uniform broadcasts (1 wavefront). Each thread covers 4
// i-values at stride 32. Inner product uses packed fma.rn.f32x2 (FFMA2),
// accumulating j-pairs; P is stored SoA with -Py pre-negated so a j-pair is
// one aligned 64-bit shared load with no repacking.

#define N2 32
#define TT 128
#define NTHREADS 128
#define NJ 32

typedef unsigned long long u64;

__device__ __forceinline__ u64 pack2(float x, float y) {
    u64 r; asm("mov.b64 %0, {%1, %2};" : "=l"(r) : "f"(x), "f"(y)); return r;
}
__device__ __forceinline__ u64 fma2(u64 a, u64 b, u64 c) {
    u64 d; asm("fma.rn.f32x2 %0, %1, %2, %3;" : "=l"(d) : "l"(a), "l"(b), "l"(c)); return d;
}
__device__ __forceinline__ float2 unpack2(u64 v) {
    float2 f; asm("mov.b64 {%0, %1}, %2;" : "=f"(f.x), "=f"(f.y) : "l"(v)); return f;
}

__global__ __launch_bounds__(NTHREADS)
void s4d_vandermonde_kernel(
    const float* __restrict__ log_dt,
    const float* __restrict__ C,          // (H, N2, 2)
    const float* __restrict__ log_A_real, // (H, N2)
    const float* __restrict__ A_imag,     // (H, N2)
    float* __restrict__ out,              // (H, L)
    int L)
{
    __shared__ float2 sQ[N2][TT];       // 32 KB : Ccf * exp(dtA*i)
    __shared__ float  sPx[N2][NJ];      //  4 KB :  Re exp(dtA*T*j)
    __shared__ float  sPny[N2][NJ];     //  4 KB : -Im exp(dtA*T*j)
    __shared__ float2 sW[N2];           // exp(dtA)
    __shared__ float  sAr[N2], sAi[N2];
    __shared__ float2 sCcf[N2];

    const int h    = blockIdx.x;
    const int tid  = threadIdx.x;
    const int lane = tid & 31;
    const int jt   = tid >> 5;          // warp id = j-tile

    // ---------- Phase 0: per-(h,n) coefficients ----------
    if (tid < N2) {
        const int n = tid;
        const int g = h * N2 + n;
        float dt  = expf(log_dt[h]);
        float ar0 = -expf(log_A_real[g]);   // Re(A)
        float ai0 = A_imag[g];              // Im(A)
        float ar  = ar0 * dt;               // Re(dtA)
        float ai  = ai0 * dt;               // Im(dtA)
        float er  = expf(ar), s, c;
        sincosf(ai, &s, &c);
        float wr = er * c, wi = er * s;     // w = exp(dtA)
        sW[n]  = make_float2(wr, wi);
        sAr[n] = ar;
        sAi[n] = ai;
        // D = (exp(dtA) - 1) / A   (complex divide via conj)
        float Er = wr - 1.0f, Ei = wi;
        float inv = 1.0f / (ar0 * ar0 + ai0 * ai0);
        float Dr = (Er * ar0 + Ei * ai0) * inv;
        float Di = (Ei * ar0 - Er * ai0) * inv;
        // Ccf = 2 * Cc * D  (fold the final factor 2)
        float cr = C[2 * g], ci = C[2 * g + 1];
        sCcf[n] = make_float2(2.0f * (cr * Dr - ci * Di),
                              2.0f * (cr * Di + ci * Dr));
    }
    __syncthreads();

    // ---------- Phase 1: Q[n][i], 4 anchors + depth-32 recurrence ----------
    {
        const int n   = tid >> 2;   // 0..31
        const int seg = tid & 3;    // 0..3 -> i = 32*seg .. 32*seg+31
        float ar = sAr[n], ai = sAi[n];
        float x  = 32.0f * (float)seg;
        float e  = expf(ar * x), s, c;
        sincosf(ai * x, &s, &c);
        float zr0 = e * c, zi0 = e * s;     // exp(dtA * 32*seg)
        float2 cc = sCcf[n];
        float zr = cc.x * zr0 - cc.y * zi0; // Ccf * anchor
        float zi = cc.x * zi0 + cc.y * zr0;
        float2 w = sW[n];
        const int ibase = seg * 32;
        #pragma unroll
        for (int k = 0; k < 32; k++) {
            sQ[n][ibase + k] = make_float2(zr, zi);
            float nzr = zr * w.x - zi * w.y;
            float nzi = zr * w.y + zi * w.x;
            zr = nzr; zi = nzi;
        }
    }

    // ---------- Phase 2: P[n][j] = exp(dtA * T * j), SoA, -Py folded ----------
    #pragma unroll
    for (int r = 0; r < (N2 * NJ) / NTHREADS; r++) {
        int idx = r * NTHREADS + tid;
        int n = idx >> 5;
        int j = idx & 31;
        float x = (float)(TT * j);
        float e = expf(sAr[n] * x), s, c;
        sincosf(sAi[n] * x, &s, &c);
        sPx[n][j]  = e * c;
        sPny[n][j] = -e * s;
    }
    __syncthreads();

    // ---------- Phase 3: rank-32 contraction with FFMA2 ----------
    // Thread covers i in {lane, lane+32, lane+64, lane+96} and the warp's
    // 8 j-values as 4 packed pairs. acc[i][jp] : lo = j=8*jt+2*jp, hi = +1.
    u64 acc[4][4];
    #pragma unroll
    for (int a = 0; a < 4; a++)
        #pragma unroll
        for (int b = 0; b < 4; b++) acc[a][b] = 0ULL;

    const float* pxBase  = &sPx[0][jt * 8];
    const float* pnyBase = &sPny[0][jt * 8];

    #pragma unroll 4
    for (int n = 0; n < N2; n++) {
        float2 q0 = sQ[n][lane];
        float2 q1 = sQ[n][lane + 32];
        float2 q2 = sQ[n][lane + 64];
        float2 q3 = sQ[n][lane + 96];
        u64 qr[4] = { pack2(q0.x, q0.x), pack2(q1.x, q1.x),
                      pack2(q2.x, q2.x), pack2(q3.x, q3.x) };
        u64 qi[4] = { pack2(q0.y, q0.y), pack2(q1.y, q1.y),
                      pack2(q2.y, q2.y), pack2(q3.y, q3.y) };
        const u64* px  = (const u64*)(pxBase  + n * NJ);  // warp-uniform
        const u64* pny = (const u64*)(pnyBase + n * NJ);  // broadcasts
        #pragma unroll
        for (int jp = 0; jp < 4; jp++) {
            u64 pxv  = px[jp];
            u64 pnyv = pny[jp];
            #pragma unroll
            for (int i = 0; i < 4; i++) {
                acc[i][jp] = fma2(pxv,  qr[i], acc[i][jp]);
                acc[i][jp] = fma2(pnyv, qi[i], acc[i][jp]);
            }
        }
    }

    // ---------- Store: coalesced across lanes ----------
    float* outh = out + (size_t)h * (size_t)L + jt * 8 * TT;
    #pragma unroll
    for (int jp = 0; jp < 4; jp++) {
        #pragma unroll
        for (int i = 0; i < 4; i++) {
            float2 v = unpack2(acc[i][jp]);
            outh[(2 * jp + 0) * TT + lane + 32 * i] = v.x;
            outh[(2 * jp + 1) * TT + lane + 32 * i] = v.y;
        }
    }
}

extern "C" void kernel_launch(void* const* d_in, const int* in_sizes, int n_in,
                              void* d_out, int out_size) {
    // inputs: [0]=L (scalar), [1]=log_dt (H), [2]=C (H,N2,2),
    //         [3]=log_A_real (H,N2), [4]=A_imag (H,N2)
    const float* log_dt     = (const float*)d_in[1];
    const float* C          = (const float*)d_in[2];
    const float* log_A_real = (const float*)d_in[3];
    const float* A_imag     = (const float*)d_in[4];
    float* out = (float*)d_out;

    int H = in_sizes[1];          // 1024
    int L = out_size / H;         // 4096  (NJ = L/TT = 32 assumed by layout)

    s4d_vandermonde_kernel<<<H, NTHREADS>>>(log_dt, C, log_A_real, A_imag, out, L);
}